// round 6
// baseline (speedup 1.0000x reference)
#include <cuda_runtime.h>
#include <stdint.h>

#define N_NODES 50000
#define N_EDGES 800000
#define D 64
#define BN_EPS 1e-5f
#define TILE_ROWS 64
#define GEMM_BLOCKS ((N_NODES + TILE_ROWS - 1) / TILE_ROWS)   // 782

// Scratch (static device globals — no allocations allowed)
__device__ float g_agg [N_NODES * D];   // agg (+x folded in)
__device__ float g_hpre[N_NODES * D];   // pre-BN GEMM1 output
__device__ float g_stats[2 * D];        // [0:64) col sums, [64:128) col sumsq

// ---------------------------------------------------------------------------
// init: g_agg = xin  (folds the GIN "+ x_i" into the aggregation buffer),
//       zero stats accumulators
// ---------------------------------------------------------------------------
__global__ void k_init(const float* __restrict__ xin) {
    int i = blockIdx.x * blockDim.x + threadIdx.x;     // 800000 float4s exactly
    reinterpret_cast<float4*>(g_agg)[i] =
        reinterpret_cast<const float4*>(xin)[i];
    if (blockIdx.x == 0 && threadIdx.x < 2 * D) g_stats[threadIdx.x] = 0.0f;
}

// ---------------------------------------------------------------------------
// scatter: for each edge (s -> d): g_agg[d] += xin[s]
// 16 threads per edge; each thread moves one float4 via red.global.add.v4.
// edge_index is INT32 (JAX x64 disabled downgrades int64 arrays).
// ---------------------------------------------------------------------------
__global__ __launch_bounds__(256) void k_scatter(
    const float* __restrict__ xin,
    const int* __restrict__ src,
    const int* __restrict__ dst)
{
    int tid = blockIdx.x * blockDim.x + threadIdx.x;
    int e = tid >> 4;                  // edge id
    if (e >= N_EDGES) return;
    int q = (tid & 15) << 2;           // float offset in row: 0,4,...,60

    int s = __ldg(&src[e]);            // 16 lanes read same word (L1 broadcast)
    int d = __ldg(&dst[e]);

    float4 v = *reinterpret_cast<const float4*>(xin + (size_t)s * D + q);
    size_t gaddr = __cvta_generic_to_global(g_agg + (size_t)d * D + q);
    asm volatile("red.global.add.v4.f32 [%0], {%1,%2,%3,%4};"
                 :: "l"(gaddr), "f"(v.x), "f"(v.y), "f"(v.z), "f"(v.w)
                 : "memory");
}

// ---------------------------------------------------------------------------
// GEMM1: g_hpre = g_agg @ W1 + b1, and accumulate per-column sum / sumsq.
// Block = 256 threads, 64-row tile, each thread computes a 4x4 micro-tile.
// ---------------------------------------------------------------------------
__global__ __launch_bounds__(256) void k_gemm1(
    const float* __restrict__ W1, const float* __restrict__ b1)
{
    __shared__ float Ws[D * D];
    __shared__ float Xs[TILE_ROWS][D + 1];
    __shared__ float s_sum[D], s_sq[D];

    int tid = threadIdx.x;
    int row0 = blockIdx.x * TILE_ROWS;

    #pragma unroll
    for (int i = tid; i < D * D; i += 256) Ws[i] = W1[i];
    if (tid < D) { s_sum[tid] = 0.0f; s_sq[tid] = 0.0f; }

    #pragma unroll
    for (int i = tid; i < TILE_ROWS * D; i += 256) {
        int r = i >> 6, c = i & 63;
        int row = row0 + r;
        Xs[r][c] = (row < N_NODES) ? g_agg[(size_t)row * D + c] : 0.0f;
    }
    __syncthreads();

    int tx = tid & 15;   // col group (4 cols)
    int ty = tid >> 4;   // row group (4 rows)

    float4 acc[4];
    #pragma unroll
    for (int r = 0; r < 4; r++) acc[r] = make_float4(0.f, 0.f, 0.f, 0.f);

    #pragma unroll 8
    for (int k = 0; k < D; k++) {
        float4 w = *reinterpret_cast<const float4*>(&Ws[k * D + tx * 4]);
        #pragma unroll
        for (int r = 0; r < 4; r++) {
            float xv = Xs[ty * 4 + r][k];
            acc[r].x = fmaf(xv, w.x, acc[r].x);
            acc[r].y = fmaf(xv, w.y, acc[r].y);
            acc[r].z = fmaf(xv, w.z, acc[r].z);
            acc[r].w = fmaf(xv, w.w, acc[r].w);
        }
    }

    float4 bb = *reinterpret_cast<const float4*>(&b1[tx * 4]);
    float4 csum = make_float4(0.f, 0.f, 0.f, 0.f);
    float4 csq  = make_float4(0.f, 0.f, 0.f, 0.f);

    #pragma unroll
    for (int r = 0; r < 4; r++) {
        int row = row0 + ty * 4 + r;
        if (row < N_NODES) {
            float4 h;
            h.x = acc[r].x + bb.x;
            h.y = acc[r].y + bb.y;
            h.z = acc[r].z + bb.z;
            h.w = acc[r].w + bb.w;
            *reinterpret_cast<float4*>(&g_hpre[(size_t)row * D + tx * 4]) = h;
            csum.x += h.x;  csq.x = fmaf(h.x, h.x, csq.x);
            csum.y += h.y;  csq.y = fmaf(h.y, h.y, csq.y);
            csum.z += h.z;  csq.z = fmaf(h.z, h.z, csq.z);
            csum.w += h.w;  csq.w = fmaf(h.w, h.w, csq.w);
        }
    }
    atomicAdd(&s_sum[tx * 4 + 0], csum.x);
    atomicAdd(&s_sum[tx * 4 + 1], csum.y);
    atomicAdd(&s_sum[tx * 4 + 2], csum.z);
    atomicAdd(&s_sum[tx * 4 + 3], csum.w);
    atomicAdd(&s_sq [tx * 4 + 0], csq.x);
    atomicAdd(&s_sq [tx * 4 + 1], csq.y);
    atomicAdd(&s_sq [tx * 4 + 2], csq.z);
    atomicAdd(&s_sq [tx * 4 + 3], csq.w);
    __syncthreads();

    if (tid < D) {
        atomicAdd(&g_stats[tid],     s_sum[tid]);
        atomicAdd(&g_stats[D + tid], s_sq[tid]);
    }
}

// ---------------------------------------------------------------------------
// GEMM2: out = relu( relu(BN(g_hpre)) @ W2 + b2 )
// BN scale/shift derived from g_stats per block (cheap: 64 lanes).
// ---------------------------------------------------------------------------
__global__ __launch_bounds__(256) void k_gemm2(
    const float* __restrict__ W2, const float* __restrict__ b2,
    const float* __restrict__ gam, const float* __restrict__ beta,
    float* __restrict__ out)
{
    __shared__ float Ws[D * D];
    __shared__ float Xs[TILE_ROWS][D + 1];
    __shared__ float s_scale[D], s_shift[D];

    int tid = threadIdx.x;
    int row0 = blockIdx.x * TILE_ROWS;

    if (tid < D) {
        const float invN = 1.0f / (float)N_NODES;
        float mean = g_stats[tid] * invN;
        float var  = fmaf(-mean, mean, g_stats[D + tid] * invN);
        float sc   = gam[tid] * rsqrtf(var + BN_EPS);
        s_scale[tid] = sc;
        s_shift[tid] = beta[tid] - mean * sc;
    }
    #pragma unroll
    for (int i = tid; i < D * D; i += 256) Ws[i] = W2[i];
    __syncthreads();   // scale/shift must be ready before the X-tile load

    #pragma unroll
    for (int i = tid; i < TILE_ROWS * D; i += 256) {
        int r = i >> 6, c = i & 63;
        int row = row0 + r;
        float v = 0.0f;
        if (row < N_NODES) {
            v = fmaf(g_hpre[(size_t)row * D + c], s_scale[c], s_shift[c]);
            v = fmaxf(v, 0.0f);
        }
        Xs[r][c] = v;
    }
    __syncthreads();

    int tx = tid & 15;
    int ty = tid >> 4;

    float4 acc[4];
    #pragma unroll
    for (int r = 0; r < 4; r++) acc[r] = make_float4(0.f, 0.f, 0.f, 0.f);

    #pragma unroll 8
    for (int k = 0; k < D; k++) {
        float4 w = *reinterpret_cast<const float4*>(&Ws[k * D + tx * 4]);
        #pragma unroll
        for (int r = 0; r < 4; r++) {
            float xv = Xs[ty * 4 + r][k];
            acc[r].x = fmaf(xv, w.x, acc[r].x);
            acc[r].y = fmaf(xv, w.y, acc[r].y);
            acc[r].z = fmaf(xv, w.z, acc[r].z);
            acc[r].w = fmaf(xv, w.w, acc[r].w);
        }
    }

    float4 bb = *reinterpret_cast<const float4*>(&b2[tx * 4]);
    #pragma unroll
    for (int r = 0; r < 4; r++) {
        int row = row0 + ty * 4 + r;
        if (row < N_NODES) {
            float4 h;
            h.x = fmaxf(acc[r].x + bb.x, 0.0f);
            h.y = fmaxf(acc[r].y + bb.y, 0.0f);
            h.z = fmaxf(acc[r].z + bb.z, 0.0f);
            h.w = fmaxf(acc[r].w + bb.w, 0.0f);
            *reinterpret_cast<float4*>(&out[(size_t)row * D + tx * 4]) = h;
        }
    }
}

// ---------------------------------------------------------------------------
// launch
// ---------------------------------------------------------------------------
static void run_layer(const float* xin,
                      const int* src, const int* dst,
                      const float* W1, const float* b1,
                      const float* gam, const float* beta,
                      const float* W2, const float* b2,
                      float* out)
{
    k_init<<<(N_NODES * D / 4 + 255) / 256, 256>>>(xin);
    k_scatter<<<(N_EDGES * 16 + 255) / 256, 256>>>(xin, src, dst);
    k_gemm1<<<GEMM_BLOCKS, 256>>>(W1, b1);
    k_gemm2<<<GEMM_BLOCKS, 256>>>(W2, b2, gam, beta, out);
}

extern "C" void kernel_launch(void* const* d_in, const int* in_sizes, int n_in,
                              void* d_out, int out_size)
{
    const float* x    = (const float*)d_in[0];
    const int*   ei   = (const int*)d_in[1];      // int32: JAX x64 is disabled
    const float* W1_0 = (const float*)d_in[2];
    const float* b1_0 = (const float*)d_in[3];
    const float* g_0  = (const float*)d_in[4];
    const float* be_0 = (const float*)d_in[5];
    const float* W2_0 = (const float*)d_in[6];
    const float* b2_0 = (const float*)d_in[7];
    const float* W1_1 = (const float*)d_in[8];
    const float* b1_1 = (const float*)d_in[9];
    const float* g_1  = (const float*)d_in[10];
    const float* be_1 = (const float*)d_in[11];
    const float* W2_1 = (const float*)d_in[12];
    const float* b2_1 = (const float*)d_in[13];

    const int* src = ei;              // edge_index[0]
    const int* dst = ei + N_EDGES;    // edge_index[1]

    float* h1 = (float*)d_out;        // output tuple (h1, h2), concatenated
    float* h2 = h1 + (size_t)N_NODES * D;

    run_layer(x,  src, dst, W1_0, b1_0, g_0, be_0, W2_0, b2_0, h1);
    run_layer(h1, src, dst, W1_1, b1_1, g_1, be_1, W2_1, b2_1, h2);
}